// round 11
// baseline (speedup 1.0000x reference)
#include <cuda_runtime.h>

#define BATCH 2
#define NBOX  1000
#define NCLS  80
#define NCAND 100
#define CAND  2048          // max filtered candidates per batch
#define BCAP  1024          // per-class staging capacity (<=1000 used)
#define NB    128           // histogram buckets (score bits >>19, rebased)
#define HBASE 1952          // (0x3D000000 >> 19): bucket of p = 1/32
#define TARGET 1200
#define PC 0.03125f         // stage only p >= 1/32 (bucket-aligned)

#define NSCORE 250          // score blocks (8 warps each = 2000 boxes)
#define NCLSB  (BATCH * NCLS)
#define NFIN   BATCH
#define NBLK   (NSCORE + NCLSB + NFIN)   // 412 — co-resident by construction

typedef unsigned long long u64;
typedef unsigned int u32;

// globals zero-initialized at load; every invocation self-cleans.
__device__ int    g_bcnt[BATCH * NCLS];            // per-class staged counts
__device__ u64    g_bstage[BATCH * NCLS * BCAP];   // per-class staged keys
__device__ u32    g_hist [BATCH * NB];             // candidate score histogram
__device__ u32    g_hist2[BATCH * NB];             // survivor score histogram
__device__ int    g_scnt2[BATCH];                  // survivor counts
__device__ u64    g_surv[BATCH * CAND];            // survivor keys
__device__ float4 g_cbox[BATCH * NCLS * BCAP];     // survivor boxes by (c, rank)
__device__ int    g_c1, g_c2, g_c3;                // phase completion counters

struct SmemCls { u64 skey[BCAP]; float4 sbx[BCAP]; unsigned char sflag[BCAP]; };
struct SmemFin { u64 skey[CAND]; };
union  SmemU   { SmemCls c; SmemFin f; };

__device__ __forceinline__ int bkt(u32 sb) {
    int v = (int)(sb >> 19) - HBASE;
    v = v < 0 ? 0 : v;
    return v > NB - 1 ? NB - 1 : v;
}

// warp 0 helper: suffix-scan a 128-bucket histogram (4 buckets/lane).
//   mode 0: max(max v: suf>=TARGET, min v: suf<=CAND)  (candidates)
//   mode 1: max v: suf >= NCAND                        (survivors)
__device__ __forceinline__ int warp_threshold(const u32* hist, int mode) {
    int lane = threadIdx.x & 31;
    u32 h[4]; u32 L = 0;
    #pragma unroll
    for (int q = 0; q < 4; q++) { h[q] = hist[lane * 4 + q]; L += h[q]; }
    u32 x = L;
    #pragma unroll
    for (int off = 1; off < 32; off <<= 1) {
        u32 t = __shfl_down_sync(0xffffffffu, x, off);
        if (lane + off < 32) x += t;
    }
    u32 run = x - L;
    int t1 = 0, t2 = NB - 1;
    #pragma unroll
    for (int q = 3; q >= 0; q--) {
        u32 suf = run + h[q];
        int v = lane * 4 + q;
        if (mode == 0) {
            if (suf >= TARGET && v > t1) t1 = v;
            if (suf <= CAND   && v < t2) t2 = v;
        } else {
            if (suf >= NCAND  && v > t1) t1 = v;
        }
        run = suf;
    }
    #pragma unroll
    for (int off = 16; off; off >>= 1) {
        int a  = __shfl_xor_sync(0xffffffffu, t1, off);
        int bb = __shfl_xor_sync(0xffffffffu, t2, off);
        t1 = a  > t1 ? a  : t1;
        t2 = bb < t2 ? bb : t2;
    }
    return (mode == 0) ? (t1 > t2 ? t1 : t2) : t1;
}

// release: all block data written -> bump counter
__device__ __forceinline__ void block_arrive(int* cnt) {
    __threadfence();
    __syncthreads();
    if (threadIdx.x == 0) atomicAdd(cnt, 1);
}
// acquire: wait until counter reaches v
__device__ __forceinline__ void block_wait(int* cnt, int v) {
    if (threadIdx.x == 0) {
        while (atomicAdd(cnt, 0) < v) __nanosleep(64);
    }
    __syncthreads();
    __threadfence();
}

// ---------------------------------------------------------------------------
// One grid, three phase block-groups. 412 blocks x 256 threads, co-resident.
// ---------------------------------------------------------------------------
__global__ __launch_bounds__(256, 4) void fused_kernel(
        const float* __restrict__ cls,
        const float* __restrict__ box,
        const float* __restrict__ anc,
        const float* __restrict__ info,
        float* __restrict__ out) {
    __shared__ SmemU smu;
    __shared__ int s_n, s_cnt, s_base, s_tb;

    int bid  = blockIdx.x;
    int tid  = threadIdx.x;
    int lane = tid & 31;

    // =================== PHASE 1: score (blocks 0..249) ===================
    if (bid < NSCORE) {
        int gw = bid * 8 + (tid >> 5);           // exactly BATCH*NBOX warps
        int b  = gw / NBOX, n = gw % NBOX;
        const float* lg = cls + (size_t)(b * NBOX + n) * 81;

        float v0 = lg[lane];
        float v1 = lg[lane + 32];
        bool  ok2 = (lane + 64) < 81;
        float v2 = ok2 ? lg[lane + 64] : -1e30f;

        float mx = fmaxf(fmaxf(v0, v1), v2);
        #pragma unroll
        for (int o = 16; o; o >>= 1) mx = fmaxf(mx, __shfl_xor_sync(0xffffffffu, mx, o));

        float e0 = expf(v0 - mx);
        float e1 = expf(v1 - mx);
        float e2 = ok2 ? expf(v2 - mx) : 0.f;

        float s = e0 + e1 + e2;
        #pragma unroll
        for (int o = 16; o; o >>= 1) s += __shfl_xor_sync(0xffffffffu, s, o);
        float inv = 1.f / s;

        float pr[3] = { e0 * inv, e1 * inv, e2 * inv };

        #pragma unroll
        for (int h = 0; h < 3; h++) {
            int idx = lane + 32 * h;             // logit index 0..80
            float p = pr[h];
            if (idx >= 1 && idx <= 80 && p >= PC) {
                u32 sb = __float_as_uint(p);
                int ci = b * NCLS + (idx - 1);
                int pos = atomicAdd(&g_bcnt[ci], 1);
                g_bstage[(size_t)ci * BCAP + pos] = ((u64)sb << 10) | (u32)(1023 - n);
                atomicAdd(&g_hist[b * NB + bkt(sb)], 1u);
            }
        }
        block_arrive(&g_c1);
        return;
    }

    // ================ PHASE 2: per-class NMS (blocks 250..409) =============
    if (bid < NSCORE + NCLSB) {
        int ci = bid - NSCORE;
        int b  = ci / NCLS;
        int c  = ci % NCLS;

        block_wait(&g_c1, NSCORE);

        if (tid == 0) s_n = 0;
        if (tid < 32) {
            int tb = warp_threshold(g_hist + b * NB, 0);
            if (tid == 0) s_tb = tb;
        }
        __syncthreads();

        int m  = g_bcnt[ci];
        int tb = s_tb;
        for (int i = tid; i < m; i += 256) {
            u64 k = g_bstage[(size_t)ci * BCAP + i];
            if (bkt((u32)(k >> 10)) >= tb) {
                int p = atomicAdd(&s_n, 1);
                smu.c.skey[p] = k;
            }
        }
        __syncthreads();
        int n = s_n;
        if (tid == 0) g_bcnt[ci] = 0;            // cleanup for next invocation

        if (n > 0) {
            // pad to pow2, bitonic sort descending (score, ~boxidx)
            int P = 32; while (P < n) P <<= 1;
            for (int e = tid; e < P; e += 256) if (e >= n) smu.c.skey[e] = 0ull;
            for (unsigned k = 2; k <= (unsigned)P; k <<= 1) {
                for (unsigned j = k >> 1; j > 0; j >>= 1) {
                    __syncthreads();
                    for (int e = tid; e < P; e += 256) {
                        int ixj = e ^ (int)j;
                        if (ixj > e) {
                            u64 va = smu.c.skey[e], vb = smu.c.skey[ixj];
                            bool desc = ((e & (int)k) == 0);
                            if (desc ? (va < vb) : (va > vb)) {
                                smu.c.skey[e] = vb; smu.c.skey[ixj] = va;
                            }
                        }
                    }
                }
            }
            __syncthreads();

            // decode boxes (rank order)
            float hmax = info[b * 5 + 0] - 1.f;
            float wmax = info[b * 5 + 1] - 1.f;
            for (int i = tid; i < n; i += 256) {
                u64 k = smu.c.skey[i];
                int nb = 1023 - (int)(k & 0x3FFull);
                float4 a = *(const float4*)(anc + (size_t)(b * NBOX + nb) * 4);
                float ha  = a.z - a.x + 1.f;
                float wa  = a.w - a.y + 1.f;
                float cya = a.x + 0.5f * ha;
                float cxa = a.y + 0.5f * wa;
                float4 e = *(const float4*)(box +
                             ((size_t)(b * NBOX + nb) * 81 + (c + 1)) * 4);
                float cy = (e.x / 10.f) * ha + cya;
                float cx = (e.y / 10.f) * wa + cxa;
                float h  = expf(e.z / 5.f) * ha;
                float wd = expf(e.w / 5.f) * wa;
                float ymin = fminf(fmaxf(cy - 0.5f * h,        0.f), hmax);
                float ymax = fminf(fmaxf(cy + 0.5f * h - 1.f,  0.f), hmax);
                float xmin = fminf(fmaxf(cx - 0.5f * wd,       0.f), wmax);
                float xmax = fminf(fmaxf(cx + 0.5f * wd - 1.f, 0.f), wmax);
                smu.c.sbx[i]   = make_float4(ymin, xmin, ymax, xmax);
                smu.c.sflag[i] = 0;
            }
            __syncthreads();

            // greedy NMS: warp 0, serial over i, j-parallel over lanes
            if (tid < 32) {
                for (int i = 0; i < n - 1; i++) {
                    if (smu.c.sflag[i] == 0) {
                        float4 B = smu.c.sbx[i];
                        float ai = (B.z - B.x) * (B.w - B.y);
                        for (int j = i + 1 + tid; j < n; j += 32) {
                            float4 C = smu.c.sbx[j];
                            float iy = fmaxf(0.f, fminf(B.z, C.z) - fmaxf(B.x, C.x));
                            float ix = fmaxf(0.f, fminf(B.w, C.w) - fmaxf(B.y, C.y));
                            float inter = iy * ix;
                            float aj  = (C.z - C.x) * (C.w - C.y);
                            float iou = inter / fmaxf(ai + aj - inter, 1e-8f);
                            if (iou > 0.5f) smu.c.sflag[j] = 1;
                        }
                    }
                    __syncwarp();
                }
            }
            __syncthreads();

            // reserve global survivor slots
            if (tid == 0) s_cnt = 0;
            __syncthreads();
            int my = 0;
            for (int e = tid; e < n; e += 256) if (!smu.c.sflag[e]) my++;
            if (my) atomicAdd(&s_cnt, my);
            __syncthreads();
            if (tid == 0) s_base = atomicAdd(&g_scnt2[b], s_cnt);
            __syncthreads();
            if (tid == 0) s_cnt = 0;
            __syncthreads();

            // emit survivors
            for (int e = tid; e < n; e += 256) {
                if (!smu.c.sflag[e]) {
                    u32 sb   = (u32)(smu.c.skey[e] >> 10);
                    u32 flat = (u32)(c * BCAP + e);    // rank == true class rank
                    int slot = atomicAdd(&s_cnt, 1);
                    g_surv[b * CAND + s_base + slot] =
                        ((u64)sb << 18) | (u64)(0x3FFFFu ^ flat);
                    g_cbox[(size_t)ci * BCAP + e] = smu.c.sbx[e];
                    atomicAdd(&g_hist2[b * NB + bkt(sb)], 1u);
                }
            }
        }
        block_arrive(&g_c2);
        return;
    }

    // ================== PHASE 3: final top-100 (blocks 410..411) ===========
    {
        int b = bid - NSCORE - NCLSB;

        block_wait(&g_c2, NCLSB);

        if (tid == 0) s_n = 0;
        if (tid < 32) {
            int tb = warp_threshold(g_hist2 + b * NB, 1);
            if (tid == 0) s_tb = tb;
        }
        __syncthreads();

        int tb2 = s_tb;
        int tot = g_scnt2[b];
        for (int i = tid; i < tot; i += 256) {
            u64 k = g_surv[b * CAND + i];
            if (bkt((u32)(k >> 18)) >= tb2) {
                int p = atomicAdd(&s_n, 1);
                smu.f.skey[p] = k;                // <= CAND by construction
            }
        }
        __syncthreads();
        int n = s_n;                              // typ. ~100-200

        int P = 128; while (P < n) P <<= 1;
        for (int e = tid; e < P; e += 256) if (e >= n) smu.f.skey[e] = 0ull;
        for (unsigned k = 2; k <= (unsigned)P; k <<= 1) {
            for (unsigned j = k >> 1; j > 0; j >>= 1) {
                __syncthreads();
                for (int e = tid; e < P; e += 256) {
                    int ixj = e ^ (int)j;
                    if (ixj > e) {
                        u64 va = smu.f.skey[e], vb = smu.f.skey[ixj];
                        bool desc = ((e & (int)k) == 0);
                        if (desc ? (va < vb) : (va > vb)) {
                            smu.f.skey[e] = vb; smu.f.skey[ixj] = va;
                        }
                    }
                }
            }
        }
        __syncthreads();

        // emit top-100
        if (tid < NCAND) {
            u64 kv   = smu.f.skey[tid];
            u32 sb   = (u32)(kv >> 18);
            u32 flat = 0x3FFFFu ^ ((u32)kv & 0x3FFFFu);
            int c    = (int)(flat >> 10);
            int rank = (int)(flat & (BCAP - 1));
            float4 bx = g_cbox[(size_t)(b * NCLS + c) * BCAP + rank];
            float* o = out + (size_t)(b * NCAND + tid) * 6;
            o[0] = bx.x; o[1] = bx.y; o[2] = bx.z; o[3] = bx.w;
            o[4] = __uint_as_float(sb);
            o[5] = (float)(c + 1);
        }

        // cleanup for next invocation
        if (tid < NB) {
            g_hist [b * NB + tid] = 0;
            g_hist2[b * NB + tid] = 0;
        }
        if (tid == 0) g_scnt2[b] = 0;

        __threadfence();
        __syncthreads();
        if (tid == 0) {
            int d = atomicAdd(&g_c3, 1);
            if (d == NFIN - 1) {                  // last final block resets
                g_c1 = 0; g_c2 = 0; g_c3 = 0;
            }
        }
    }
}

// ---------------------------------------------------------------------------
extern "C" void kernel_launch(void* const* d_in, const int* in_sizes, int n_in,
                              void* d_out, int out_size) {
    const float* cls  = (const float*)d_in[0];
    const float* box  = (const float*)d_in[1];
    const float* anc  = (const float*)d_in[2];
    const float* info = (const float*)d_in[3];

    fused_kernel<<<NBLK, 256>>>(cls, box, anc, info, (float*)d_out);
}

// round 12
// speedup vs baseline: 1.2400x; 1.2400x over previous
#include <cuda_runtime.h>

#define BATCH 2
#define NBOX  1000
#define NCLS  80
#define NCAND 100
#define CAND  2048          // hard smem cap for filtered candidates per batch
#define BCAP  1024          // per-class staging capacity (<=1000 used)
#define NB    128           // histogram buckets (score bits >>19, rebased)
#define HBASE 1952          // (0x3D000000 >> 19): bucket of p = 1/32
#define TARGET 512          // candidate prefix size (>=100 survivors w/ margin)
#define PC 0.03125f         // stage only p >= 1/32 (bucket-aligned)

typedef unsigned long long u64;
typedef unsigned int u32;

// globals zero-initialized at load; every invocation self-cleans.
__device__ int    g_bcnt[BATCH * NCLS];            // per-class staged counts
__device__ u64    g_bstage[BATCH * NCLS * BCAP];   // per-class staged keys
__device__ u32    g_hist [BATCH * NB];             // candidate score histogram
__device__ u32    g_hist2[BATCH * NB];             // survivor score histogram
__device__ int    g_scnt2[BATCH];                  // survivor counts
__device__ u64    g_surv[BATCH * CAND];            // survivor keys
__device__ float4 g_cbox[BATCH * NCLS * BCAP];     // survivor boxes by (c, rank)

__device__ __forceinline__ int bkt(u32 sb) {
    int v = (int)(sb >> 19) - HBASE;
    v = v < 0 ? 0 : v;
    return v > NB - 1 ? NB - 1 : v;
}

// ---------------------------------------------------------------------------
// K1: single-pass softmax; stage (score, ~boxidx) into per-class buckets;
// histogram score bits. One warp per (b, n). 250 blocks x 256.
// ---------------------------------------------------------------------------
__global__ __launch_bounds__(256) void score_kernel(const float* __restrict__ cls) {
    int gw   = (blockIdx.x * blockDim.x + threadIdx.x) >> 5;
    int lane = threadIdx.x & 31;
    if (gw >= BATCH * NBOX) return;
    int b = gw / NBOX, n = gw % NBOX;

    const float* lg = cls + (size_t)(b * NBOX + n) * 81;

    float v0 = lg[lane];
    float v1 = lg[lane + 32];
    bool  ok2 = (lane + 64) < 81;
    float v2 = ok2 ? lg[lane + 64] : -1e30f;

    float mx = fmaxf(fmaxf(v0, v1), v2);
    #pragma unroll
    for (int o = 16; o; o >>= 1) mx = fmaxf(mx, __shfl_xor_sync(0xffffffffu, mx, o));

    float e0 = expf(v0 - mx);
    float e1 = expf(v1 - mx);
    float e2 = ok2 ? expf(v2 - mx) : 0.f;

    float s = e0 + e1 + e2;
    #pragma unroll
    for (int o = 16; o; o >>= 1) s += __shfl_xor_sync(0xffffffffu, s, o);
    float inv = 1.f / s;

    float pr[3] = { e0 * inv, e1 * inv, e2 * inv };

    #pragma unroll
    for (int h = 0; h < 3; h++) {
        int idx = lane + 32 * h;                 // logit index 0..80
        float p = pr[h];
        if (idx >= 1 && idx <= 80 && p >= PC) {
            u32 sb = __float_as_uint(p);
            int ci = b * NCLS + (idx - 1);
            int pos = atomicAdd(&g_bcnt[ci], 1);  // < 1000 always
            g_bstage[(size_t)ci * BCAP + pos] = ((u64)sb << 10) | (u32)(1023 - n);
            atomicAdd(&g_hist[b * NB + bkt(sb)], 1u);
        }
    }
}

// ---------------------------------------------------------------------------
// warp 0 helper: suffix-scan a 128-bucket histogram (4 buckets/lane).
//   mode 0: max(max v: suf>=TARGET, min v: suf<=CAND)  (candidates)
//   mode 1: max v: suf >= NCAND                        (survivors)
// ---------------------------------------------------------------------------
__device__ __forceinline__ int warp_threshold(const u32* hist, int mode) {
    int lane = threadIdx.x & 31;
    u32 h[4]; u32 L = 0;
    #pragma unroll
    for (int q = 0; q < 4; q++) { h[q] = hist[lane * 4 + q]; L += h[q]; }

    u32 x = L;                                    // inclusive suffix over lanes
    #pragma unroll
    for (int off = 1; off < 32; off <<= 1) {
        u32 t = __shfl_down_sync(0xffffffffu, x, off);
        if (lane + off < 32) x += t;
    }
    u32 run = x - L;                              // suffix strictly after chunk
    int t1 = 0, t2 = NB - 1;
    #pragma unroll
    for (int q = 3; q >= 0; q--) {
        u32 suf = run + h[q];
        int v = lane * 4 + q;
        if (mode == 0) {
            if (suf >= TARGET && v > t1) t1 = v;
            if (suf <= CAND   && v < t2) t2 = v;
        } else {
            if (suf >= NCAND  && v > t1) t1 = v;
        }
        run = suf;
    }
    #pragma unroll
    for (int off = 16; off; off >>= 1) {
        int a  = __shfl_xor_sync(0xffffffffu, t1, off);
        int bb = __shfl_xor_sync(0xffffffffu, t2, off);
        t1 = a  > t1 ? a  : t1;
        t2 = bb < t2 ? bb : t2;
    }
    return (mode == 0) ? (t1 > t2 ? t1 : t2) : t1;
}

// ---------------------------------------------------------------------------
// K2: per (b, class) — in-block threshold, filter, sort, decode, NMS,
// emit survivors. grid = BATCH*NCLS, block = 128.
// ---------------------------------------------------------------------------
__global__ __launch_bounds__(128) void class_nms_kernel(
        const float* __restrict__ box,
        const float* __restrict__ anc,
        const float* __restrict__ info) {
    __shared__ u64 skey[BCAP];
    __shared__ float4 sbx[BCAP];
    __shared__ unsigned char sflag[BCAP];
    __shared__ int s_n, s_cnt, s_base, s_tb;

    int tid = threadIdx.x;
    int ci  = blockIdx.x;
    int b   = ci / NCLS;
    int c   = ci % NCLS;

    if (tid == 0) s_n = 0;
    // warp 0: candidate threshold bucket (redundant per block; deterministic)
    if (tid < 32) {
        int tb = warp_threshold(g_hist + b * NB, 0);
        if (tid == 0) s_tb = tb;
    }
    __syncthreads();

    // filter staged keys by threshold bucket
    int m  = g_bcnt[ci];
    int tb = s_tb;
    for (int i = tid; i < m; i += 128) {
        u64 k = g_bstage[(size_t)ci * BCAP + i];
        if (bkt((u32)(k >> 10)) >= tb) {
            int p = atomicAdd(&s_n, 1);
            skey[p] = k;
        }
    }
    __syncthreads();
    int n = s_n;
    if (tid == 0) g_bcnt[ci] = 0;          // cleanup for next invocation
    if (n == 0) return;

    // pad to pow2, bitonic sort descending (score, ~boxidx)
    int P = 32; while (P < n) P <<= 1;
    for (int e = tid; e < P; e += 128) if (e >= n) skey[e] = 0ull;
    for (unsigned k = 2; k <= (unsigned)P; k <<= 1) {
        for (unsigned j = k >> 1; j > 0; j >>= 1) {
            __syncthreads();
            for (int e = tid; e < P; e += 128) {
                int ixj = e ^ (int)j;
                if (ixj > e) {
                    u64 va = skey[e], vb = skey[ixj];
                    bool desc = ((e & (int)k) == 0);
                    if (desc ? (va < vb) : (va > vb)) { skey[e] = vb; skey[ixj] = va; }
                }
            }
        }
    }
    __syncthreads();

    // decode boxes (rank order)
    float hmax = info[b * 5 + 0] - 1.f;
    float wmax = info[b * 5 + 1] - 1.f;
    for (int i = tid; i < n; i += 128) {
        u64 k = skey[i];
        int nb = 1023 - (int)(k & 0x3FFull);
        float4 a = *(const float4*)(anc + (size_t)(b * NBOX + nb) * 4);
        float ha  = a.z - a.x + 1.f;
        float wa  = a.w - a.y + 1.f;
        float cya = a.x + 0.5f * ha;
        float cxa = a.y + 0.5f * wa;
        float4 e = *(const float4*)(box + ((size_t)(b * NBOX + nb) * 81 + (c + 1)) * 4);
        float cy = (e.x / 10.f) * ha + cya;
        float cx = (e.y / 10.f) * wa + cxa;
        float h  = expf(e.z / 5.f) * ha;
        float wd = expf(e.w / 5.f) * wa;
        float ymin = fminf(fmaxf(cy - 0.5f * h,        0.f), hmax);
        float ymax = fminf(fmaxf(cy + 0.5f * h - 1.f,  0.f), hmax);
        float xmin = fminf(fmaxf(cx - 0.5f * wd,       0.f), wmax);
        float xmax = fminf(fmaxf(cx + 0.5f * wd - 1.f, 0.f), wmax);
        sbx[i]   = make_float4(ymin, xmin, ymax, xmax);
        sflag[i] = 0;
    }
    __syncthreads();

    // greedy NMS: warp 0, serial over i, j-parallel over lanes
    if (tid < 32) {
        for (int i = 0; i < n - 1; i++) {
            if (sflag[i] == 0) {
                float4 B = sbx[i];
                float ai = (B.z - B.x) * (B.w - B.y);
                for (int j = i + 1 + tid; j < n; j += 32) {
                    float4 C = sbx[j];
                    float iy = fmaxf(0.f, fminf(B.z, C.z) - fmaxf(B.x, C.x));
                    float ix = fmaxf(0.f, fminf(B.w, C.w) - fmaxf(B.y, C.y));
                    float inter = iy * ix;
                    float aj  = (C.z - C.x) * (C.w - C.y);
                    float iou = inter / fmaxf(ai + aj - inter, 1e-8f);  // exact ref
                    if (iou > 0.5f) sflag[j] = 1;
                }
            }
            __syncwarp();
        }
    }
    __syncthreads();

    // reserve global survivor slots
    if (tid == 0) s_cnt = 0;
    __syncthreads();
    int my = 0;
    for (int e = tid; e < n; e += 128) if (!sflag[e]) my++;
    if (my) atomicAdd(&s_cnt, my);
    __syncthreads();
    if (tid == 0) s_base = atomicAdd(&g_scnt2[b], s_cnt);
    __syncthreads();
    if (tid == 0) s_cnt = 0;
    __syncthreads();

    // emit survivors: key (score desc, (c,rank) asc proxy), box, histogram
    for (int e = tid; e < n; e += 128) {
        if (!sflag[e]) {
            u32 sb   = (u32)(skey[e] >> 10);
            u32 flat = (u32)(c * BCAP + e);            // rank == true class rank
            int slot = atomicAdd(&s_cnt, 1);
            g_surv[b * CAND + s_base + slot] =
                ((u64)sb << 18) | (u64)(0x3FFFFu ^ flat);
            g_cbox[(size_t)ci * BCAP + e] = sbx[e];
            atomicAdd(&g_hist2[b * NB + bkt(sb)], 1u);
        }
    }
}

// ---------------------------------------------------------------------------
// K3: per batch — survivor threshold for top-100, small sort, emit output,
// all cleanup. grid = BATCH, block = 128.
// ---------------------------------------------------------------------------
__global__ __launch_bounds__(128) void final_kernel(float* __restrict__ out) {
    __shared__ u64 skey[CAND];
    __shared__ int s_tb, s_n;

    int tid = threadIdx.x;
    int b   = blockIdx.x;

    if (tid == 0) s_n = 0;
    if (tid < 32) {
        int tb = warp_threshold(g_hist2 + b * NB, 1);
        if (tid == 0) s_tb = tb;
    }
    __syncthreads();

    int tb2 = s_tb;

    // filter survivors above the bucket threshold
    int tot = g_scnt2[b];
    for (int i = tid; i < tot; i += 128) {
        u64 k = g_surv[b * CAND + i];
        if (bkt((u32)(k >> 18)) >= tb2) {
            int p = atomicAdd(&s_n, 1);
            skey[p] = k;                      // <= CAND by construction
        }
    }
    __syncthreads();
    int n = s_n;                              // typ. ~100-200

    int P = 128; while (P < n) P <<= 1;       // <= CAND
    for (int e = tid; e < P; e += 128) if (e >= n) skey[e] = 0ull;
    for (unsigned k = 2; k <= (unsigned)P; k <<= 1) {
        for (unsigned j = k >> 1; j > 0; j >>= 1) {
            __syncthreads();
            for (int e = tid; e < P; e += 128) {
                int ixj = e ^ (int)j;
                if (ixj > e) {
                    u64 va = skey[e], vb = skey[ixj];
                    bool desc = ((e & (int)k) == 0);
                    if (desc ? (va < vb) : (va > vb)) { skey[e] = vb; skey[ixj] = va; }
                }
            }
        }
    }
    __syncthreads();

    // emit top-100
    if (tid < NCAND) {
        u64 kv   = skey[tid];
        u32 sb   = (u32)(kv >> 18);
        u32 flat = 0x3FFFFu ^ ((u32)kv & 0x3FFFFu);
        int c    = (int)(flat >> 10);
        int rank = (int)(flat & (BCAP - 1));
        float4 bx = g_cbox[(size_t)(b * NCLS + c) * BCAP + rank];
        float* o = out + (size_t)(b * NCAND + tid) * 6;
        o[0] = bx.x; o[1] = bx.y; o[2] = bx.z; o[3] = bx.w;
        o[4] = __uint_as_float(sb);
        o[5] = (float)(c + 1);
    }

    // cleanup for next invocation
    if (tid < NB) {
        g_hist [b * NB + tid] = 0;
        g_hist2[b * NB + tid] = 0;
    }
    if (tid == 0) g_scnt2[b] = 0;
}

// ---------------------------------------------------------------------------
extern "C" void kernel_launch(void* const* d_in, const int* in_sizes, int n_in,
                              void* d_out, int out_size) {
    const float* cls  = (const float*)d_in[0];
    const float* box  = (const float*)d_in[1];
    const float* anc  = (const float*)d_in[2];
    const float* info = (const float*)d_in[3];

    score_kernel<<<(BATCH * NBOX * 32 + 255) / 256, 256>>>(cls);
    class_nms_kernel<<<BATCH * NCLS, 128>>>(box, anc, info);
    final_kernel<<<BATCH, 128>>>((float*)d_out);
}